// round 11
// baseline (speedup 1.0000x reference)
#include <cuda_runtime.h>
#include <cuda_bf16.h>

#define B_ 32
#define N_ 256
#define TAIL_FR 32

struct __align__(32) f8 { float4 lo, hi; };

__device__ __forceinline__ f8 ldg256(const float* p) {
    f8 v;
    asm volatile("ld.global.v8.f32 {%0,%1,%2,%3,%4,%5,%6,%7}, [%8];"
                 : "=f"(v.lo.x), "=f"(v.lo.y), "=f"(v.lo.z), "=f"(v.lo.w),
                   "=f"(v.hi.x), "=f"(v.hi.y), "=f"(v.hi.z), "=f"(v.hi.w)
                 : "l"(p));
    return v;
}

__device__ __forceinline__ void stg256_cs(float* p, const f8& v) {
    asm volatile("st.global.cs.v8.f32 [%0], {%1,%2,%3,%4,%5,%6,%7,%8};"
                 :: "l"(p),
                    "f"(v.lo.x), "f"(v.lo.y), "f"(v.lo.z), "f"(v.lo.w),
                    "f"(v.hi.x), "f"(v.hi.y), "f"(v.hi.z), "f"(v.hi.w)
                 : "memory");
}

// ---------------------------------------------------------------------------
// Single fused kernel. Grid (N_ + ceil(T/TAIL_FR), B_), 128 threads.
// 256-bit (v8) stores: 128 threads x 32B = 4KB = 2 frames per iteration.
// Threads [0,64) handle frame p, [64,128) frame p+1 (half-warp uniform).
//   blockIdx.x <  N_  -> segment block (b, idx): block reduction for c1/d,
//                        load <=3 source rows once (v8), stream-store frames.
//   blockIdx.x >= N_  -> tail block: 32 frames; mask + v8 zero-fill of the
//                        contiguous inactive sub-range.
// int32/int64 detection: durations < 16, so if int64 every odd 32-bit word of
// the first 512 words is 0 (region in-bounds under both layouts).
// All reductions/barriers complete before any divergent exit.
// ---------------------------------------------------------------------------
__global__ __launch_bounds__(128) void main_kernel(
    const float* __restrict__ start,
    const float* __restrict__ mid,
    const float* __restrict__ end,
    const void* __restrict__ dur_raw,
    const void* __restrict__ rc_raw,
    float* __restrict__ out,
    float* __restrict__ mask_out,
    int T, int F8, int write_mask)
{
    const int b   = blockIdx.y;
    const int tid = threadIdx.x;
    const bool is_seg = (blockIdx.x < N_);
    const int idx = is_seg ? blockIdx.x : -1;

    __shared__ int shO[4];
    __shared__ int shC[4], shD[4], shT[4];

    // ---- detect int32 vs int64 (first 512 words, broadcast/L1-hot) ----
    const int4* d4 = (const int4*)dur_raw;
    int4 det = __ldg(d4 + tid);
    int odd = det.y | det.w;
    odd = __reduce_or_sync(0xffffffffu, odd);
    if ((tid & 31) == 0) shO[tid >> 5] = odd;
    __syncthreads();
    const int is64 = ((shO[0] | shO[1] | shO[2] | shO[3]) == 0) ? 1 : 0;
    __syncthreads();

    // ---- load this batch's durations, predicated accumulate ----
    int accC = 0, accD = 0, accT = 0;
    if (is64) {
        int4 w = __ldg(d4 + b * 128 + tid);
        const int e0 = 2 * tid, e1 = 2 * tid + 1;
        accT = w.x + w.z;
        if (e0 <= idx) accC += w.x;
        if (e1 <= idx) accC += w.z;
        if (e0 == idx) accD += w.x;
        if (e1 == idx) accD += w.z;
    } else if (tid < 64) {
        int4 w = __ldg(d4 + b * 64 + tid);
        const int e0 = 4 * tid;
        accT = w.x + w.y + w.z + w.w;
        if (e0 + 0 <= idx) accC += w.x;
        if (e0 + 1 <= idx) accC += w.y;
        if (e0 + 2 <= idx) accC += w.z;
        if (e0 + 3 <= idx) accC += w.w;
        if (e0 + 0 == idx) accD += w.x;
        if (e0 + 1 == idx) accD += w.y;
        if (e0 + 2 == idx) accD += w.z;
        if (e0 + 3 == idx) accD += w.w;
    }
    accC = __reduce_add_sync(0xffffffffu, accC);
    accD = __reduce_add_sync(0xffffffffu, accD);
    accT = __reduce_add_sync(0xffffffffu, accT);
    if ((tid & 31) == 0) {
        shC[tid >> 5] = accC; shD[tid >> 5] = accD; shT[tid >> 5] = accT;
    }
    __syncthreads();
    const int c1     = shC[0] + shC[1] + shC[2] + shC[3];
    const int d      = shD[0] + shD[1] + shD[2] + shD[3];
    const int totalF = shT[0] + shT[1] + shT[2] + shT[3];

    const int col = tid & 63;      // f8 column within a frame (F8 = 64)
    const int fh  = tid >> 6;      // 0 or 1: which frame of the pair

    if (!is_seg) {
        // ---- tail / mask block: frames [tb, tb+TAIL_FR) ----
        const int tb = (blockIdx.x - N_) * TAIL_FR;
        int total = totalF; if (total > T) total = T;
        if (write_mask && tid < TAIL_FR && tb + tid < T) {
            mask_out[b * T + tb + tid] = (tb + tid < total) ? 1.0f : 0.0f;
        }
        if (tb + TAIL_FR <= total) return;    // fully active: nothing to zero
        f8 z;
        z.lo = make_float4(0.f, 0.f, 0.f, 0.f);
        z.hi = z.lo;
        float* ob = out + ((b * T + tb) * F8 + col) * 8;
#pragma unroll
        for (int k = 0; k < TAIL_FR; k += 2) {
            const int t = tb + k + fh;
            if (t >= total && t < T)
                stg256_cs(ob + (k + fh) * F8 * 8, z);
        }
        return;
    }

    // ---- segment block ----
    if (d <= 0) return;
    const int off = c1 - d;
    if (off >= T) return;

    const int cls = is64 ? (int)((const long long*)rc_raw)[b * N_ + idx]
                         : ((const int*)rc_raw)[b * N_ + idx];
    const bool lin = (cls == 1) && (d >= 4);

    const int rb = ((b * N_ + idx) * F8 + col) * 8;
    const bool need_s = lin || (d > 1);
    const bool need_e = lin || (d > 1);
    const bool need_m = lin || (d != 2);
    f8 s, m, e;
    if (need_s) s = ldg256(start + rb);
    if (need_m) m = ldg256(mid + rb);
    if (need_e) e = ldg256(end + rb);

    int pe = d; if (off + pe > T) pe = T - off;
    const int half = d >> 1;
    int den1 = half - 1;     if (den1 < 1) den1 = 1;
    int den2 = d - half - 1; if (den2 < 1) den2 = 1;
    const float inv1 = 1.0f / (float)den1;
    const float inv2 = 1.0f / (float)den2;

    float* ob = out + ((b * T + off) * F8 + col) * 8;

    if (lin) {
        for (int p = 0; p < pe; p += 2) {
            const int pp = p + fh;
            if (pp >= pe) break;
            const bool fhalf = (pp < half);
            const float w1 = fhalf ? (float)pp * inv1
                                   : (float)(pp - half) * inv2;
            const float w0 = 1.0f - w1;
            const f8 A  = fhalf ? s : m;
            const f8 Bv = fhalf ? m : e;
            f8 r;
            r.lo.x = fmaf(A.lo.x, w0, Bv.lo.x * w1);
            r.lo.y = fmaf(A.lo.y, w0, Bv.lo.y * w1);
            r.lo.z = fmaf(A.lo.z, w0, Bv.lo.z * w1);
            r.lo.w = fmaf(A.lo.w, w0, Bv.lo.w * w1);
            r.hi.x = fmaf(A.hi.x, w0, Bv.hi.x * w1);
            r.hi.y = fmaf(A.hi.y, w0, Bv.hi.y * w1);
            r.hi.z = fmaf(A.hi.z, w0, Bv.hi.z * w1);
            r.hi.w = fmaf(A.hi.w, w0, Bv.hi.w * w1);
            stg256_cs(ob + pp * F8 * 8, r);
        }
    } else {
        for (int p = 0; p < pe; p += 2) {
            const int pp = p + fh;
            if (pp >= pe) break;
            f8 r = m;
            if (d > 1) {
                if (pp == 0)          r = s;
                else if (pp == d - 1) r = e;
            }
            stg256_cs(ob + pp * F8 * 8, r);
        }
    }
}

// ---------------------------------------------------------------------------
// Launch
// ---------------------------------------------------------------------------
extern "C" void kernel_launch(void* const* d_in, const int* in_sizes, int n_in,
                              void* d_out, int out_size) {
    const float* start = (const float*)d_in[0];
    const float* mid   = (const float*)d_in[1];
    const float* end   = (const float*)d_in[2];
    const void*  dur   = d_in[3];
    const void*  rc    = d_in[4];
    (void)n_in;

    const int BN = in_sizes[3];                 // B*N
    const int F  = in_sizes[0] / BN;            // 512
    const int F8 = F / 8;

    long long os = (long long)out_size;
    int T, write_mask;
    if (os % ((long long)B_ * (F + 1)) == 0) {
        T = (int)(os / ((long long)B_ * (F + 1)));
        write_mask = 1;
    } else {
        T = (int)(os / ((long long)B_ * F));
        write_mask = 0;
    }

    float* out_f  = (float*)d_out;
    float* mask_f = out_f + B_ * T * F;

    const int tail_blocks = (T + TAIL_FR - 1) / TAIL_FR;
    dim3 grid(N_ + tail_blocks, B_);
    main_kernel<<<grid, 128>>>(
        start, mid, end, dur, rc, out_f, mask_f, T, F8, write_mask);
}